// round 16
// baseline (speedup 1.0000x reference)
#include <cuda_runtime.h>
#include <cuda_fp16.h>
#include <cstdint>

#define H      128
#define NH     8
#define HDIM   16
#define MAXDEG 16
#define MAXN_PAD 50048      // 391 * 128, >= N

// ---------------- scratch (device globals: no allocations allowed) ----------
// Q fp32, PERMUTED: feature f = d*8+hd -> slot hd*16+d (head-contiguous).
// K fp16, PERMUTED same layout.  V fp16, ORIGINAL layout.
__device__ __align__(16) float  g_Q[MAXN_PAD * H];
__device__ __align__(16) __half g_K[MAXN_PAD * H];
__device__ __align__(16) __half g_V[MAXN_PAD * H];

// ---------------- helpers ----------------------------------------------------
__device__ __forceinline__ unsigned long long fma2(unsigned long long a,
                                                   unsigned long long b,
                                                   unsigned long long c) {
    unsigned long long d;
    asm("fma.rn.f32x2 %0, %1, %2, %3;" : "=l"(d) : "l"(a), "l"(b), "l"(c));
    return d;
}
__device__ __forceinline__ unsigned long long dup2(float x) {
    unsigned long long r;
    unsigned int xi = __float_as_uint(x);
    asm("mov.b64 %0, {%1, %1};" : "=l"(r) : "r"(xi));
    return r;
}
__device__ __forceinline__ void unpack2(unsigned long long v, float& lo, float& hi) {
    unsigned int a, b;
    asm("mov.b64 {%0, %1}, %2;" : "=r"(a), "=r"(b) : "l"(v));
    lo = __uint_as_float(a);
    hi = __uint_as_float(b);
}
__device__ __forceinline__ uint32_t smem_u32(const void* p) {
    uint32_t a;
    asm("{ .reg .u64 t; cvta.to.shared.u64 t, %1; cvt.u32.u64 %0, t; }"
        : "=r"(a) : "l"(p));
    return a;
}
__device__ __forceinline__ void ldmatrix_x4(uint32_t& r0, uint32_t& r1,
                                            uint32_t& r2, uint32_t& r3,
                                            uint32_t addr) {
    asm volatile("ldmatrix.sync.aligned.m8n8.x4.shared.b16 {%0,%1,%2,%3}, [%4];"
                 : "=r"(r0), "=r"(r1), "=r"(r2), "=r"(r3) : "r"(addr));
}
__device__ __forceinline__ void mma_f16(float c[4], uint32_t a0, uint32_t a1,
                                        uint32_t a2, uint32_t a3,
                                        uint32_t b0, uint32_t b1) {
    asm volatile(
        "mma.sync.aligned.m16n8k16.row.col.f32.f16.f16.f32 "
        "{%0,%1,%2,%3},{%4,%5,%6,%7},{%8,%9},{%0,%1,%2,%3};"
        : "+f"(c[0]), "+f"(c[1]), "+f"(c[2]), "+f"(c[3])
        : "r"(a0), "r"(a1), "r"(a2), "r"(a3), "r"(b0), "r"(b1));
}
#define BAR_SYNC(id) \
    asm volatile("bar.sync %0, %1;" :: "r"(id), "r"(128) : "memory")

// ---------------- smem layout (dynamic) --------------------------------------
#define HP 136                                  // half pitch (HMMA staging)
#define OFF_A16  0                              // 128 x HP halves   = 34816
#define OFF_B16  34816                          // 64 x HP halves    = 17408
#define OFF_A32  52224                          // [16][132] floats  = 8448
#define OFF_B32  60672                          // [16][68] floats   = 4352
#define PROJ_SMEM 65024

// =============================================================================
// Fused dual-pipe projection: per block, warps 0-3 compute output cols 0-63
// on the FMA pipe (fp32 FFMA2), warps 4-7 compute cols 64-127 on the tensor
// path (fp16 HMMA). Groups are fully independent (named barriers 1 / 2).
// blockIdx.z: 0 -> Q (x0.25, fp32 perm), 1 -> K (fp16 perm), 2 -> V (fp16).
// =============================================================================
__global__ __launch_bounds__(256, 2) void proj_gemm(
    const float* __restrict__ hmat,
    const float* __restrict__ Wq, const float* __restrict__ bq,
    const float* __restrict__ Wk, const float* __restrict__ bk,
    const float* __restrict__ Wv, const float* __restrict__ bv,
    int N)
{
    extern __shared__ __align__(16) char dsm[];
    const int z = blockIdx.z;
    const float* __restrict__ W    = (z == 0) ? Wq : (z == 1) ? Wk : Wv;
    const float* __restrict__ bias = (z == 0) ? bq : (z == 1) ? bk : bv;
    const float scale = (z == 0) ? 0.25f : 1.0f;
    const int tid  = threadIdx.x;
    const int row0 = blockIdx.x * 128;

    if (tid < 128) {
        // ================= FFMA group: output cols 0-63, fp32 ===============
        float (*As32)[132] = reinterpret_cast<float(*)[132]>(dsm + OFF_A32);
        float (*Bs32)[68]  = reinterpret_cast<float(*)[68]>(dsm + OFF_B32);

        const int g  = tid;            // 0..127
        const int tx = tid & 7;        // n-tile 0..7 (cols tx*8..+7)
        const int ty = tid >> 3;       // m-tile 0..15
        const bool arow_ok = (row0 + g < N);
        const int brow = g >> 1;       // W row 0..63
        const int bcol = (g & 1) * 8;  // k sub-offset 0 or 8

        unsigned long long acc[8][4];
#pragma unroll
        for (int i = 0; i < 8; i++)
#pragma unroll
            for (int j = 0; j < 4; j++) acc[i][j] = 0ULL;

        // prefetch chunk 0 (BK=16)
        float4 av[4], wv[2];
#pragma unroll
        for (int i = 0; i < 4; i++)
            av[i] = arow_ok
                ? *reinterpret_cast<const float4*>(hmat + (size_t)(row0 + g) * H + i * 4)
                : make_float4(0.f, 0.f, 0.f, 0.f);
#pragma unroll
        for (int j = 0; j < 2; j++)
            wv[j] = *reinterpret_cast<const float4*>(W + (size_t)brow * H + bcol + j * 4);

        for (int chunk = 0; chunk < 8; chunk++) {
            // transposed stores
#pragma unroll
            for (int i = 0; i < 4; i++) {
                int k0 = i * 4;
                As32[k0 + 0][g] = av[i].x; As32[k0 + 1][g] = av[i].y;
                As32[k0 + 2][g] = av[i].z; As32[k0 + 3][g] = av[i].w;
            }
#pragma unroll
            for (int j = 0; j < 2; j++) {
                int k0 = bcol + j * 4;
                Bs32[k0 + 0][brow] = wv[j].x; Bs32[k0 + 1][brow] = wv[j].y;
                Bs32[k0 + 2][brow] = wv[j].z; Bs32[k0 + 3][brow] = wv[j].w;
            }
            BAR_SYNC(1);

            if (chunk < 7) {
                int kk = (chunk + 1) * 16;
#pragma unroll
                for (int i = 0; i < 4; i++)
                    av[i] = arow_ok
                        ? *reinterpret_cast<const float4*>(hmat + (size_t)(row0 + g) * H + kk + i * 4)
                        : make_float4(0.f, 0.f, 0.f, 0.f);
#pragma unroll
                for (int j = 0; j < 2; j++)
                    wv[j] = *reinterpret_cast<const float4*>(W + (size_t)brow * H + kk + bcol + j * 4);
            }

#pragma unroll
            for (int k = 0; k < 16; k++) {
                ulonglong2 b01 = *reinterpret_cast<const ulonglong2*>(&Bs32[k][tx * 8]);
                ulonglong2 b23 = *reinterpret_cast<const ulonglong2*>(&Bs32[k][tx * 8 + 4]);
                float4 a0 = *reinterpret_cast<const float4*>(&As32[k][ty * 8]);
                float4 a1 = *reinterpret_cast<const float4*>(&As32[k][ty * 8 + 4]);
                unsigned long long ad[8];
                ad[0] = dup2(a0.x); ad[1] = dup2(a0.y); ad[2] = dup2(a0.z); ad[3] = dup2(a0.w);
                ad[4] = dup2(a1.x); ad[5] = dup2(a1.y); ad[6] = dup2(a1.z); ad[7] = dup2(a1.w);
#pragma unroll
                for (int i = 0; i < 8; i++) {
                    acc[i][0] = fma2(ad[i], b01.x, acc[i][0]);
                    acc[i][1] = fma2(ad[i], b01.y, acc[i][1]);
                    acc[i][2] = fma2(ad[i], b23.x, acc[i][2]);
                    acc[i][3] = fma2(ad[i], b23.y, acc[i][3]);
                }
            }
            BAR_SYNC(1);
        }

        // epilogue: cols c = tx*8+u (0..63)
        float bl[8];
#pragma unroll
        for (int u = 0; u < 8; u++) bl[u] = __ldg(bias + tx * 8 + u);

#pragma unroll
        for (int i = 0; i < 8; i++) {
            int gr = row0 + ty * 8 + i;
            if (gr >= N) continue;
            float vals[8];
#pragma unroll
            for (int j = 0; j < 4; j++) {
                float lo, hi;
                unpack2(acc[i][j], lo, hi);
                vals[2 * j]     = (lo + bl[2 * j])     * scale;
                vals[2 * j + 1] = (hi + bl[2 * j + 1]) * scale;
            }
            if (z == 0) {        // Q fp32 perm: c=tx*8+u -> slot u*16+tx
                float* crow = g_Q + (size_t)gr * H;
#pragma unroll
                for (int u = 0; u < 8; u++) crow[u * 16 + tx] = vals[u];
            } else if (z == 1) { // K fp16 perm
                __half* crow = g_K + (size_t)gr * H;
#pragma unroll
                for (int u = 0; u < 8; u++) crow[u * 16 + tx] = __float2half_rn(vals[u]);
            } else {             // V fp16 original
                __half hv[8];
#pragma unroll
                for (int u = 0; u < 8; u++) hv[u] = __float2half_rn(vals[u]);
                *reinterpret_cast<uint4*>(g_V + (size_t)gr * H + tx * 8) =
                    *reinterpret_cast<const uint4*>(hv);
            }
        }
    } else {
        // ================= HMMA group: output cols 64-127, fp16 =============
        __half* As16 = reinterpret_cast<__half*>(dsm + OFF_A16);  // [128][HP]
        __half* Bs16 = reinterpret_cast<__half*>(dsm + OFF_B16);  // [64][HP]

        const int g     = tid - 128;          // 0..127
        const int warp4 = (tid >> 5) - 4;     // 0..3
        const int lane  = tid & 31;
        const int wm    = warp4 * 32;
        const int group = lane >> 2;
        const int tg    = lane & 3;

        // stage A fp16 (all 128 cols): thread g -> row g
        {
            const int row = g;
            const bool ok = (row0 + row < N);
#pragma unroll
            for (int i = 0; i < 16; i++) {
                float4 x = ok
                    ? *reinterpret_cast<const float4*>(hmat + (size_t)(row0 + row) * H + i * 8)
                    : make_float4(0.f, 0.f, 0.f, 0.f);
                float4 y = ok
                    ? *reinterpret_cast<const float4*>(hmat + (size_t)(row0 + row) * H + i * 8 + 4)
                    : make_float4(0.f, 0.f, 0.f, 0.f);
                __half2 hh[4];
                hh[0] = __floats2half2_rn(x.x, x.y);
                hh[1] = __floats2half2_rn(x.z, x.w);
                hh[2] = __floats2half2_rn(y.x, y.y);
                hh[3] = __floats2half2_rn(y.z, y.w);
                *reinterpret_cast<uint4*>(As16 + row * HP + i * 8) =
                    *reinterpret_cast<const uint4*>(hh);
            }
            // stage B fp16 (W rows 64-127): thread g -> row 64+(g>>1), half (g&1)
            const int wr = 64 + (g >> 1);
            const int cb = (g & 1) * 64;
#pragma unroll
            for (int i = 0; i < 8; i++) {
                float4 x = *reinterpret_cast<const float4*>(W + (size_t)wr * H + cb + i * 8);
                float4 y = *reinterpret_cast<const float4*>(W + (size_t)wr * H + cb + i * 8 + 4);
                __half2 hh[4];
                hh[0] = __floats2half2_rn(x.x, x.y);
                hh[1] = __floats2half2_rn(x.z, x.w);
                hh[2] = __floats2half2_rn(y.x, y.y);
                hh[3] = __floats2half2_rn(y.z, y.w);
                *reinterpret_cast<uint4*>(Bs16 + (g >> 1) * HP + cb + i * 8) =
                    *reinterpret_cast<const uint4*>(hh);
            }
        }
        BAR_SYNC(2);

        float acc[2][8][4];
#pragma unroll
        for (int mt = 0; mt < 2; mt++)
#pragma unroll
            for (int nt = 0; nt < 8; nt++)
#pragma unroll
                for (int j = 0; j < 4; j++) acc[mt][nt][j] = 0.0f;

        const uint32_t baseA = smem_u32(As16);
        const uint32_t baseB = smem_u32(Bs16);
        const uint32_t addrA = baseA + ((wm + (lane & 15)) * HP + (lane >> 4) * 8) * 2;
        const uint32_t addrB = baseB + (((lane & 7) + (lane >> 4) * 8) * HP
                                        + ((lane >> 3) & 1) * 8) * 2;

#pragma unroll
        for (int ks = 0; ks < 8; ks++) {
            const uint32_t koff = ks * 32;      // 16 halves = 32 bytes
            uint32_t afr[2][4];
#pragma unroll
            for (int mt = 0; mt < 2; mt++)
                ldmatrix_x4(afr[mt][0], afr[mt][1], afr[mt][2], afr[mt][3],
                            addrA + mt * 16 * (HP * 2) + koff);
#pragma unroll
            for (int ntp = 0; ntp < 4; ntp++) {
                uint32_t b00, b01, b10, b11;
                ldmatrix_x4(b00, b01, b10, b11, addrB + ntp * 16 * (HP * 2) + koff);
#pragma unroll
                for (int mt = 0; mt < 2; mt++) {
                    mma_f16(acc[mt][2 * ntp],     afr[mt][0], afr[mt][1],
                            afr[mt][2], afr[mt][3], b00, b01);
                    mma_f16(acc[mt][2 * ntp + 1], afr[mt][0], afr[mt][1],
                            afr[mt][2], afr[mt][3], b10, b11);
                }
            }
        }

        // epilogue: cols c0 = 64 + nt*8 + 2tg (64..127)
#pragma unroll
        for (int nt = 0; nt < 8; nt++) {
            const int c0 = 64 + nt * 8 + 2 * tg;
            const int c1 = c0 + 1;
            const float b0 = __ldg(bias + c0);
            const float b1 = __ldg(bias + c1);
            const int p0 = (c0 & 7) * HDIM + (c0 >> 3);
            const int p1 = (c1 & 7) * HDIM + (c1 >> 3);
#pragma unroll
            for (int mt = 0; mt < 2; mt++) {
                const int r0 = row0 + wm + mt * 16 + group;
                const int r1 = r0 + 8;
                float v0a = (acc[mt][nt][0] + b0) * scale;
                float v0b = (acc[mt][nt][1] + b1) * scale;
                float v1a = (acc[mt][nt][2] + b0) * scale;
                float v1b = (acc[mt][nt][3] + b1) * scale;
                if (r0 < N) {
                    if (z == 0) {
                        g_Q[(size_t)r0 * H + p0] = v0a;
                        g_Q[(size_t)r0 * H + p1] = v0b;
                    } else if (z == 1) {
                        g_K[(size_t)r0 * H + p0] = __float2half_rn(v0a);
                        g_K[(size_t)r0 * H + p1] = __float2half_rn(v0b);
                    } else {
                        *reinterpret_cast<__half2*>(g_V + (size_t)r0 * H + c0) =
                            __floats2half2_rn(v0a, v0b);
                    }
                }
                if (r1 < N) {
                    if (z == 0) {
                        g_Q[(size_t)r1 * H + p0] = v1a;
                        g_Q[(size_t)r1 * H + p1] = v1b;
                    } else if (z == 1) {
                        g_K[(size_t)r1 * H + p0] = __float2half_rn(v1a);
                        g_K[(size_t)r1 * H + p1] = __float2half_rn(v1b);
                    } else {
                        *reinterpret_cast<__half2*>(g_V + (size_t)r1 * H + c0) =
                            __floats2half2_rn(v1a, v1b);
                    }
                }
            }
        }
    }
}

// ---------------- fused sparse attention (exact R12: 46.2us measured) -------
__global__ __launch_bounds__(256) void attn_kernel(
    const int* __restrict__ row_ptr,
    const int* __restrict__ col_ind,
    float* __restrict__ out,
    int N)
{
    __shared__ float att[8][NH][MAXDEG];   // [local warp][head][edge]

    const int wl   = threadIdx.x >> 5;
    const int lane = threadIdx.x & 31;
    const int node = blockIdx.x * 8 + wl;
    if (node >= N) return;

    const int start = row_ptr[node];
    int deg = row_ptr[node + 1] - start;
    if (deg > MAXDEG) deg = MAXDEG;

    int colv = 0;
    if (lane < MAXDEG && lane < deg) colv = col_ind[start + lane];

    const float4 q4 = *reinterpret_cast<const float4*>(g_Q + (size_t)node * H + lane * 4);

    const float NEG_INF = __int_as_float(0xff800000);
    float sc[MAXDEG];
#pragma unroll
    for (int e = 0; e < MAXDEG; e++) {
        int col = __shfl_sync(0xffffffffu, colv, e);
        uint2 kr = __ldg(reinterpret_cast<const uint2*>(g_K + (size_t)col * H) + lane);
        float2 k01 = __half22float2(*reinterpret_cast<const __half2*>(&kr.x));
        float2 k23 = __half22float2(*reinterpret_cast<const __half2*>(&kr.y));
        float p = q4.x * k01.x + q4.y * k01.y + q4.z * k23.x + q4.w * k23.y;
        p += __shfl_xor_sync(0xffffffffu, p, 1);
        p += __shfl_xor_sync(0xffffffffu, p, 2);   // quad = 16 d's of head lane>>2
        sc[e] = (e < deg) ? p : NEG_INF;
    }

    float m = NEG_INF;
#pragma unroll
    for (int e = 0; e < MAXDEG; e++) m = fmaxf(m, sc[e]);
    float s = 0.0f;
#pragma unroll
    for (int e = 0; e < MAXDEG; e++) { float x = __expf(sc[e] - m); sc[e] = x; s += x; }
    float r = __frcp_rn(s);
#pragma unroll
    for (int e = 0; e < MAXDEG; e++) sc[e] *= r;

    {
        int hd = lane >> 2;
        int e0 = (lane & 3) * 4;
        *reinterpret_cast<float4*>(&att[wl][hd][e0]) =
            make_float4(sc[e0], sc[e0 + 1], sc[e0 + 2], sc[e0 + 3]);
    }
    __syncwarp();

    const int base = (lane & 1) * 4;
    float4 acc = make_float4(0.f, 0.f, 0.f, 0.f);
#pragma unroll
    for (int e0 = 0; e0 < MAXDEG; e0 += 4) {
        float4 a0 = *reinterpret_cast<const float4*>(&att[wl][base + 0][e0]);
        float4 a1 = *reinterpret_cast<const float4*>(&att[wl][base + 1][e0]);
        float4 a2 = *reinterpret_cast<const float4*>(&att[wl][base + 2][e0]);
        float4 a3 = *reinterpret_cast<const float4*>(&att[wl][base + 3][e0]);
        const float* w0 = reinterpret_cast<const float*>(&a0);
        const float* w1 = reinterpret_cast<const float*>(&a1);
        const float* w2 = reinterpret_cast<const float*>(&a2);
        const float* w3 = reinterpret_cast<const float*>(&a3);
#pragma unroll
        for (int u = 0; u < 4; u++) {
            int col = __shfl_sync(0xffffffffu, colv, e0 + u);
            uint2 vr = __ldg(reinterpret_cast<const uint2*>(g_V + (size_t)col * H) + lane);
            float2 v01 = __half22float2(*reinterpret_cast<const __half2*>(&vr.x));
            float2 v23 = __half22float2(*reinterpret_cast<const __half2*>(&vr.y));
            acc.x += w0[u] * v01.x;
            acc.y += w1[u] * v01.y;
            acc.z += w2[u] * v23.x;
            acc.w += w3[u] * v23.y;
        }
    }
    *reinterpret_cast<float4*>(out + (size_t)node * H + lane * 4) = acc;
}

// ---------------- launch -----------------------------------------------------
extern "C" void kernel_launch(void* const* d_in, const int* in_sizes, int n_in,
                              void* d_out, int out_size) {
    const float* h   = (const float*)d_in[0];
    const float* Wq  = (const float*)d_in[1];
    const float* bq  = (const float*)d_in[2];
    const float* Wk  = (const float*)d_in[3];
    const float* bk  = (const float*)d_in[4];
    const float* Wv  = (const float*)d_in[5];
    const float* bv  = (const float*)d_in[6];
    const int* row_ptr = (const int*)d_in[7];
    const int* col_ind = (const int*)d_in[8];
    float* out = (float*)d_out;

    const int N = in_sizes[0] / H;
    const int gblocks = (N + 127) / 128;

    static bool attr_set = false;
    if (!attr_set) {
        cudaFuncSetAttribute(proj_gemm,
                             cudaFuncAttributeMaxDynamicSharedMemorySize, PROJ_SMEM);
        attr_set = true;
    }

    proj_gemm<<<dim3(gblocks, 1, 3), 256, PROJ_SMEM>>>(h, Wq, bq, Wk, bk, Wv, bv, N);

    const int ablocks = (N + 7) / 8;
    attn_kernel<<<ablocks, 256>>>(row_ptr, col_ind, out, N);
}

// round 17
// speedup vs baseline: 1.1392x; 1.1392x over previous
#include <cuda_runtime.h>
#include <cuda_fp16.h>
#include <cstdint>

#define H      128
#define NH     8
#define HDIM   16
#define MAXDEG 16
#define MAXN_PAD 50048      // 391 * 128, >= N

// ---------------- scratch (device globals: no allocations allowed) ----------
// Q fp32, PERMUTED: feature f = d*8+hd -> slot hd*16+d (head-contiguous).
// K fp16, PERMUTED same layout.  V fp16, ORIGINAL layout.
__device__ __align__(16) float  g_Q[MAXN_PAD * H];
__device__ __align__(16) __half g_K[MAXN_PAD * H];
__device__ __align__(16) __half g_V[MAXN_PAD * H];

// ---------------- helpers ----------------------------------------------------
__device__ __forceinline__ uint32_t smem_u32(const void* p) {
    uint32_t a;
    asm("{ .reg .u64 t; cvta.to.shared.u64 t, %1; cvt.u32.u64 %0, t; }"
        : "=r"(a) : "l"(p));
    return a;
}
__device__ __forceinline__ void ldmatrix_x4(uint32_t& r0, uint32_t& r1,
                                            uint32_t& r2, uint32_t& r3,
                                            uint32_t addr) {
    asm volatile("ldmatrix.sync.aligned.m8n8.x4.shared.b16 {%0,%1,%2,%3}, [%4];"
                 : "=r"(r0), "=r"(r1), "=r"(r2), "=r"(r3) : "r"(addr));
}
__device__ __forceinline__ void mma_f16(float c[4], uint32_t a0, uint32_t a1,
                                        uint32_t a2, uint32_t a3,
                                        uint32_t b0, uint32_t b1) {
    asm volatile(
        "mma.sync.aligned.m16n8k16.row.col.f32.f16.f16.f32 "
        "{%0,%1,%2,%3},{%4,%5,%6,%7},{%8,%9},{%0,%1,%2,%3};"
        : "+f"(c[0]), "+f"(c[1]), "+f"(c[2]), "+f"(c[3])
        : "r"(a0), "r"(a1), "r"(a2), "r"(a3), "r"(b0), "r"(b1));
}

// ---------------- projection: fp16 HMMA for Q, K, V --------------------------
// blockIdx.z: 0 -> Q (fp32 out, permuted, x0.25), 1 -> K (fp16 perm),
//             2 -> V (fp16 original). Validated R14 tile: block 128x128,
// full K=128 fp16 staged (pitch 136 halves), warp tile 32m x 64n.
#define HP 136
#define AB_BYTES (128 * HP * 2)                 // 34816
#define PROJ_SMEM (2 * AB_BYTES)                // 69632

__global__ __launch_bounds__(256) void proj_gemm(
    const float* __restrict__ hmat,
    const float* __restrict__ Wq, const float* __restrict__ bq,
    const float* __restrict__ Wk, const float* __restrict__ bk,
    const float* __restrict__ Wv, const float* __restrict__ bv,
    int N)
{
    const int z = blockIdx.z;
    const float* __restrict__ W    = (z == 0) ? Wq : (z == 1) ? Wk : Wv;
    const float* __restrict__ bias = (z == 0) ? bq : (z == 1) ? bk : bv;
    const float scale = (z == 0) ? 0.25f : 1.0f;   // head_dim^-0.5 = 16^-0.5

    extern __shared__ __align__(16) char dsm[];
    __half* As = reinterpret_cast<__half*>(dsm);             // [128][HP] (m,k)
    __half* Bs = reinterpret_cast<__half*>(dsm + AB_BYTES);  // [128][HP] (n,k)

    const int tid  = threadIdx.x;
    const int row0 = blockIdx.x * 128;
    const int warp = tid >> 5;
    const int lane = tid & 31;
    const int wm   = (warp & 3) * 32;
    const int wn   = (warp >> 2) * 64;
    const int group = lane >> 2;
    const int tg    = lane & 3;

    // ---- stage A (h rows) and B (W rows) as fp16, 64 elems per thread ----
    {
        const int r  = tid >> 1;
        const int cb = (tid & 1) * 64;
        __half2 ah[32], wh[32];
        const bool ok = (row0 + r < N);
#pragma unroll
        for (int i = 0; i < 16; i++) {
            float4 a = ok
                ? *reinterpret_cast<const float4*>(hmat + (size_t)(row0 + r) * H + cb + i * 4)
                : make_float4(0.f, 0.f, 0.f, 0.f);
            float4 w = *reinterpret_cast<const float4*>(W + (size_t)r * H + cb + i * 4);
            ah[2 * i]     = __floats2half2_rn(a.x, a.y);
            ah[2 * i + 1] = __floats2half2_rn(a.z, a.w);
            wh[2 * i]     = __floats2half2_rn(w.x, w.y);
            wh[2 * i + 1] = __floats2half2_rn(w.z, w.w);
        }
#pragma unroll
        for (int i = 0; i < 8; i++) {
            *reinterpret_cast<uint4*>(As + r * HP + cb + i * 8) =
                reinterpret_cast<const uint4*>(ah)[i];
            *reinterpret_cast<uint4*>(Bs + r * HP + cb + i * 8) =
                reinterpret_cast<const uint4*>(wh)[i];
        }
    }
    __syncthreads();

    // ---- mainloop: ldmatrix + HMMA (validated R14 addressing) ----
    float acc[2][8][4];
#pragma unroll
    for (int mt = 0; mt < 2; mt++)
#pragma unroll
        for (int nt = 0; nt < 8; nt++)
#pragma unroll
            for (int j = 0; j < 4; j++) acc[mt][nt][j] = 0.0f;

    const uint32_t baseA = smem_u32(As);
    const uint32_t baseB = smem_u32(Bs);
    const uint32_t addrA = baseA + ((wm + (lane & 15)) * HP + (lane >> 4) * 8) * 2;
    const uint32_t addrB = baseB + ((wn + (lane & 7) + (lane >> 4) * 8) * HP
                                    + ((lane >> 3) & 1) * 8) * 2;

#pragma unroll
    for (int ks = 0; ks < 8; ks++) {
        const uint32_t koff = ks * 32;          // 16 halves = 32 bytes
        uint32_t afr[2][4];
#pragma unroll
        for (int mt = 0; mt < 2; mt++)
            ldmatrix_x4(afr[mt][0], afr[mt][1], afr[mt][2], afr[mt][3],
                        addrA + mt * 16 * (HP * 2) + koff);
#pragma unroll
        for (int ntp = 0; ntp < 4; ntp++) {
            uint32_t b00, b01, b10, b11;
            ldmatrix_x4(b00, b01, b10, b11, addrB + ntp * 16 * (HP * 2) + koff);
#pragma unroll
            for (int mt = 0; mt < 2; mt++) {
                mma_f16(acc[mt][2 * ntp],     afr[mt][0], afr[mt][1],
                        afr[mt][2], afr[mt][3], b00, b01);
                mma_f16(acc[mt][2 * ntp + 1], afr[mt][0], afr[mt][1],
                        afr[mt][2], afr[mt][3], b10, b11);
            }
        }
    }

    // ---- epilogue: bias + scale, per-z store ----
#pragma unroll
    for (int nt = 0; nt < 8; nt++) {
        const int c0 = wn + nt * 8 + 2 * tg;
        const int c1 = c0 + 1;
        const float b0 = __ldg(bias + c0);
        const float b1 = __ldg(bias + c1);
        const int p0 = (c0 & 7) * HDIM + (c0 >> 3);   // permuted slot
        const int p1 = (c1 & 7) * HDIM + (c1 >> 3);
#pragma unroll
        for (int mt = 0; mt < 2; mt++) {
            const int r0 = row0 + wm + mt * 16 + group;
            const int r1 = r0 + 8;
            const float v0a = (acc[mt][nt][0] + b0) * scale;
            const float v0b = (acc[mt][nt][1] + b1) * scale;
            const float v1a = (acc[mt][nt][2] + b0) * scale;
            const float v1b = (acc[mt][nt][3] + b1) * scale;
            if (r0 < N) {
                if (z == 0) {
                    g_Q[(size_t)r0 * H + p0] = v0a;
                    g_Q[(size_t)r0 * H + p1] = v0b;
                } else if (z == 1) {
                    g_K[(size_t)r0 * H + p0] = __float2half_rn(v0a);
                    g_K[(size_t)r0 * H + p1] = __float2half_rn(v0b);
                } else {
                    *reinterpret_cast<__half2*>(g_V + (size_t)r0 * H + c0) =
                        __floats2half2_rn(v0a, v0b);
                }
            }
            if (r1 < N) {
                if (z == 0) {
                    g_Q[(size_t)r1 * H + p0] = v1a;
                    g_Q[(size_t)r1 * H + p1] = v1b;
                } else if (z == 1) {
                    g_K[(size_t)r1 * H + p0] = __float2half_rn(v1a);
                    g_K[(size_t)r1 * H + p1] = __float2half_rn(v1b);
                } else {
                    *reinterpret_cast<__half2*>(g_V + (size_t)r1 * H + c0) =
                        __floats2half2_rn(v1a, v1b);
                }
            }
        }
    }
}

// ---------------- fused sparse attention: one warp per node -----------------
// Score pass = exact R12 (L1-optimal). Softmax split across the quad:
// lane j of each quad owns edges 4j..4j+3 (exactly what it stores), with
// max/sum closed over the quad via shfl_xor 1,2.
__global__ __launch_bounds__(256) void attn_kernel(
    const int* __restrict__ row_ptr,
    const int* __restrict__ col_ind,
    float* __restrict__ out,
    int N)
{
    __shared__ float att[8][NH][MAXDEG];   // [local warp][head][edge]

    const int wl   = threadIdx.x >> 5;
    const int lane = threadIdx.x & 31;
    const int node = blockIdx.x * 8 + wl;
    if (node >= N) return;

    const int start = row_ptr[node];
    int deg = row_ptr[node + 1] - start;
    if (deg > MAXDEG) deg = MAXDEG;

    int colv = 0;
    if (lane < MAXDEG && lane < deg) colv = col_ind[start + lane];

    const float4 q4 = *reinterpret_cast<const float4*>(g_Q + (size_t)node * H + lane * 4);

    const float NEG_INF = __int_as_float(0xff800000);
    float sc[MAXDEG];
#pragma unroll
    for (int e = 0; e < MAXDEG; e++) {
        int col = __shfl_sync(0xffffffffu, colv, e);
        uint2 kr = __ldg(reinterpret_cast<const uint2*>(g_K + (size_t)col * H) + lane);
        float2 k01 = __half22float2(*reinterpret_cast<const __half2*>(&kr.x));
        float2 k23 = __half22float2(*reinterpret_cast<const __half2*>(&kr.y));
        float p = q4.x * k01.x + q4.y * k01.y + q4.z * k23.x + q4.w * k23.y;
        p += __shfl_xor_sync(0xffffffffu, p, 1);
        p += __shfl_xor_sync(0xffffffffu, p, 2);   // quad = 16 d's of head lane>>2
        sc[e] = (e < deg) ? p : NEG_INF;
    }

    // quad-split softmax: lane j = lane&3 handles edges 4j..4j+3 of head lane>>2
    const int j  = lane & 3;
    const int e0 = j * 4;
    float l0 = sc[e0], l1 = sc[e0 + 1], l2 = sc[e0 + 2], l3 = sc[e0 + 3];
    float m = fmaxf(fmaxf(l0, l1), fmaxf(l2, l3));
    m = fmaxf(m, __shfl_xor_sync(0xffffffffu, m, 1));
    m = fmaxf(m, __shfl_xor_sync(0xffffffffu, m, 2));
    l0 = __expf(l0 - m); l1 = __expf(l1 - m);
    l2 = __expf(l2 - m); l3 = __expf(l3 - m);
    float s = (l0 + l1) + (l2 + l3);
    s += __shfl_xor_sync(0xffffffffu, s, 1);
    s += __shfl_xor_sync(0xffffffffu, s, 2);
    const float r = __frcp_rn(s);

    {
        const int hd = lane >> 2;
        *reinterpret_cast<float4*>(&att[wl][hd][e0]) =
            make_float4(l0 * r, l1 * r, l2 * r, l3 * r);
    }
    __syncwarp();

    // bspmm: coalesced fp16 V rows; weights as float4 (4 edges per LDS.128)
    const int base = (lane & 1) * 4;
    float4 acc = make_float4(0.f, 0.f, 0.f, 0.f);
#pragma unroll
    for (int eb = 0; eb < MAXDEG; eb += 4) {
        float4 a0 = *reinterpret_cast<const float4*>(&att[wl][base + 0][eb]);
        float4 a1 = *reinterpret_cast<const float4*>(&att[wl][base + 1][eb]);
        float4 a2 = *reinterpret_cast<const float4*>(&att[wl][base + 2][eb]);
        float4 a3 = *reinterpret_cast<const float4*>(&att[wl][base + 3][eb]);
        const float* w0 = reinterpret_cast<const float*>(&a0);
        const float* w1 = reinterpret_cast<const float*>(&a1);
        const float* w2 = reinterpret_cast<const float*>(&a2);
        const float* w3 = reinterpret_cast<const float*>(&a3);
#pragma unroll
        for (int u = 0; u < 4; u++) {
            int col = __shfl_sync(0xffffffffu, colv, eb + u);
            uint2 vr = __ldg(reinterpret_cast<const uint2*>(g_V + (size_t)col * H) + lane);
            float2 v01 = __half22float2(*reinterpret_cast<const __half2*>(&vr.x));
            float2 v23 = __half22float2(*reinterpret_cast<const __half2*>(&vr.y));
            acc.x += w0[u] * v01.x;
            acc.y += w1[u] * v01.y;
            acc.z += w2[u] * v23.x;
            acc.w += w3[u] * v23.y;
        }
    }
    *reinterpret_cast<float4*>(out + (size_t)node * H + lane * 4) = acc;
}

// ---------------- launch -----------------------------------------------------
extern "C" void kernel_launch(void* const* d_in, const int* in_sizes, int n_in,
                              void* d_out, int out_size) {
    const float* h   = (const float*)d_in[0];
    const float* Wq  = (const float*)d_in[1];
    const float* bq  = (const float*)d_in[2];
    const float* Wk  = (const float*)d_in[3];
    const float* bk  = (const float*)d_in[4];
    const float* Wv  = (const float*)d_in[5];
    const float* bv  = (const float*)d_in[6];
    const int* row_ptr = (const int*)d_in[7];
    const int* col_ind = (const int*)d_in[8];
    float* out = (float*)d_out;

    const int N = in_sizes[0] / H;
    const int gblocks = (N + 127) / 128;

    static bool attr_set = false;
    if (!attr_set) {
        cudaFuncSetAttribute(proj_gemm,
                             cudaFuncAttributeMaxDynamicSharedMemorySize, PROJ_SMEM);
        attr_set = true;
    }

    proj_gemm<<<dim3(gblocks, 1, 3), 256, PROJ_SMEM>>>(h, Wq, bq, Wk, bk, Wv, bv, N);

    const int ablocks = (N + 7) / 8;
    attn_kernel<<<ablocks, 256>>>(row_ptr, col_ind, out, N);
}